// round 16
// baseline (speedup 1.0000x reference)
#include <cuda_runtime.h>
#include <cuda_bf16.h>
#include <cuda_fp16.h>
#include <cstdint>

#define B_  8
#define S_  1024
#define NX_ 1024
#define H_  16
#define D_  64

// ---------------- scratch (__device__ globals; no allocation) ----------------
__device__ __half g_xh[B_ * S_ * NX_];               // x, fp16 trunc
__device__ __half g_ah[B_ * S_ * NX_];               // attention out, fp16 trunc
__device__ __half g_wqkv_h[3 * NX_ * NX_];           // [N=3072, K=1024] fp16 trunc
__device__ __half g_wproj_h[NX_ * NX_];              // [N=1024, K=1024]
__device__ __half g_qh[B_ * H_ * S_ * D_];           // [b,h,s,d], pre-scaled 0.125
__device__ __half g_kh[B_ * H_ * S_ * D_];
__device__ __half g_vh[B_ * H_ * S_ * D_];

// ---------------- PTX helpers ----------------
__device__ __forceinline__ uint32_t smem_to_u32(const void* p) {
    uint32_t a;
    asm("{ .reg .u64 t; cvta.to.shared.u64 t, %1; cvt.u32.u64 %0, t; }"
        : "=r"(a) : "l"(p));
    return a;
}
__device__ __forceinline__ void cp_async16(uint32_t dst, const void* src) {
    asm volatile("cp.async.cg.shared.global [%0], [%1], 16;"
                 :: "r"(dst), "l"(src) : "memory");
}
#define CP_COMMIT() asm volatile("cp.async.commit_group;" ::: "memory")
#define CP_WAIT(n)  asm volatile("cp.async.wait_group %0;" :: "n"(n) : "memory")

__device__ __forceinline__ void ldsm_x4(uint32_t& r0, uint32_t& r1,
                                        uint32_t& r2, uint32_t& r3, uint32_t addr) {
    asm volatile("ldmatrix.sync.aligned.m8n8.x4.shared.b16 {%0,%1,%2,%3}, [%4];"
                 : "=r"(r0), "=r"(r1), "=r"(r2), "=r"(r3) : "r"(addr));
}
__device__ __forceinline__ void ldsm_x4t(uint32_t& r0, uint32_t& r1,
                                         uint32_t& r2, uint32_t& r3, uint32_t addr) {
    asm volatile("ldmatrix.sync.aligned.m8n8.x4.trans.shared.b16 {%0,%1,%2,%3}, [%4];"
                 : "=r"(r0), "=r"(r1), "=r"(r2), "=r"(r3) : "r"(addr));
}
__device__ __forceinline__ void mma16816h(float* c, const uint32_t* a, const uint32_t* b) {
    asm volatile("mma.sync.aligned.m16n8k16.row.col.f32.f16.f16.f32 "
                 "{%0,%1,%2,%3}, {%4,%5,%6,%7}, {%8,%9}, {%0,%1,%2,%3};"
                 : "+f"(c[0]), "+f"(c[1]), "+f"(c[2]), "+f"(c[3])
                 : "r"(a[0]), "r"(a[1]), "r"(a[2]), "r"(a[3]),
                   "r"(b[0]), "r"(b[1]));
}
__device__ __forceinline__ uint32_t packh2(float x, float y) {
    __half2 h = __halves2half2(__float2half(x), __float2half(y));
    return *(uint32_t*)&h;
}

// ---------------------------------------------------------------------------
// truncate: fp32 -> fp16, same layout.
// ---------------------------------------------------------------------------
__global__ void trunc_kernel(const float* __restrict__ in,
                             __half* __restrict__ h, int n4)
{
    int i = blockIdx.x * blockDim.x + threadIdx.x;
    if (i >= n4) return;
    float4 v = ((const float4*)in)[i];
    ((__half2*)h)[2 * i]     = __half2(__float2half(v.x), __float2half(v.y));
    ((__half2*)h)[2 * i + 1] = __half2(__float2half(v.z), __float2half(v.w));
}

// ---------------------------------------------------------------------------
// transpose + truncate: W[K,N] fp32 -> T_h [N,K] fp16
// ---------------------------------------------------------------------------
__global__ void tsplit_kernel(const float* __restrict__ W,
                              __half* __restrict__ Th, int K, int N)
{
    __shared__ float t[32][33];
    int n0 = blockIdx.x * 32, k0 = blockIdx.y * 32;
    int tx = threadIdx.x, ty = threadIdx.y;  // 32 x 8
#pragma unroll
    for (int i = 0; i < 4; i++)
        t[ty + i * 8][tx] = W[(long)(k0 + ty + i * 8) * N + n0 + tx];
    __syncthreads();
#pragma unroll
    for (int i = 0; i < 4; i++) {
        float v = t[tx][ty + i * 8];
        Th[(long)(n0 + ty + i * 8) * K + k0 + tx] = __float2half(v);
    }
}

// ---------------------------------------------------------------------------
// GEMM mainloop: single-product fp16, 128x128x64 CTA tile, 256 threads,
// 8 warps (2Mx4N), 3-stage cp.async pipeline, ONE sync per stage.
// ---------------------------------------------------------------------------
#define ROWB    144
#define TILE_B  (128 * ROWB)
#define STAGE_B (2 * TILE_B)             // 36864 B
#define GEMM_SMEM_DYN (3 * STAGE_B)      // 110592 B -> 2 CTAs/SM (221 KB)

#define GEMM_MAINLOOP(Ah, Bh, K)                                                \
    extern __shared__ __align__(128) char smem[];                               \
    const uint32_t sbase = smem_to_u32(smem);                                   \
    const int tid  = threadIdx.x;                                               \
    const int lane = tid & 31;                                                  \
    const int wid  = tid >> 5;                                                  \
    const int wm   = wid & 1;                                                   \
    const int wn   = wid >> 1;                                                  \
    const int bm   = blockIdx.y * 128;                                          \
    const int bn   = blockIdx.x * 128;                                          \
    float acc[4][4][4];                                                         \
    _Pragma("unroll")                                                           \
    for (int mi = 0; mi < 4; mi++)                                              \
        _Pragma("unroll")                                                       \
        for (int ni = 0; ni < 4; ni++)                                          \
            _Pragma("unroll")                                                   \
            for (int r = 0; r < 4; r++) acc[mi][ni][r] = 0.f;                   \
    const __half* gA = Ah + (long)bm * (K);                                     \
    const __half* gB = Bh + (long)bn * (K);                                     \
    const int NS = (K) / 64;                                                    \
    auto load_stage = [&](int s) {                                              \
        const int k0 = s * 64;                                                  \
        const uint32_t buf = sbase + (s % 3) * STAGE_B;                         \
        _Pragma("unroll")                                                       \
        for (int p = 0; p < 4; p++) {                                           \
            int lin = tid + p * 256;                                            \
            int r = lin >> 3, c = lin & 7;                                      \
            cp_async16(buf + r * ROWB + c * 16,                                 \
                       gA + (long)r * (K) + k0 + c * 8);                        \
            cp_async16(buf + TILE_B + r * ROWB + c * 16,                        \
                       gB + (long)r * (K) + k0 + c * 8);                        \
        }                                                                       \
    };                                                                          \
    load_stage(0);                                                              \
    CP_COMMIT();                                                                \
    load_stage(1);                                                              \
    CP_COMMIT();                                                                \
    const int arow  = wm * 64 + (lane & 15);                                    \
    const int asel  = (lane >> 4) << 3;                                         \
    const int brow  = wn * 32 + (lane & 7) + ((lane >> 4) << 3);                \
    const int bsel  = ((lane >> 3) & 1) << 3;                                   \
    for (int s = 0; s < NS; s++) {                                              \
        if (s + 1 < NS) { CP_WAIT(1); } else { CP_WAIT(0); }                    \
        __syncthreads();                                                        \
        if (s + 2 < NS) {                                                       \
            load_stage(s + 2);                                                  \
            CP_COMMIT();                                                        \
        }                                                                       \
        const uint32_t buf = sbase + (s % 3) * STAGE_B;                         \
        _Pragma("unroll")                                                       \
        for (int ks = 0; ks < 4; ks++) {                                        \
            uint32_t a[4][4];                                                   \
            uint32_t b[4][2];                                                   \
            const int acol = ks * 16 + asel;                                    \
            const int bcol = ks * 16 + bsel;                                    \
            _Pragma("unroll")                                                   \
            for (int nj = 0; nj < 2; nj++)                                      \
                ldsm_x4(b[nj * 2][0], b[nj * 2][1],                             \
                        b[nj * 2 + 1][0], b[nj * 2 + 1][1],                     \
                        buf + TILE_B + (brow + nj * 16) * ROWB + bcol * 2);     \
            _Pragma("unroll")                                                   \
            for (int mi = 0; mi < 4; mi++)                                      \
                ldsm_x4(a[mi][0], a[mi][1], a[mi][2], a[mi][3],                 \
                        buf + (arow + mi * 16) * ROWB + acol * 2);              \
            _Pragma("unroll")                                                   \
            for (int mi = 0; mi < 4; mi++)                                      \
                _Pragma("unroll")                                               \
                for (int ni = 0; ni < 4; ni++)                                  \
                    mma16816h(acc[mi][ni], a[mi], b[ni]);                       \
        }                                                                       \
    }

// ---------------------------------------------------------------------------
// Projection GEMM: fp32 out + bias (final output)
// ---------------------------------------------------------------------------
__global__ void __launch_bounds__(256, 2) gemm_proj(
    const __half* __restrict__ Ah, const __half* __restrict__ Bh,
    const float* __restrict__ bias, float* __restrict__ C, int N, int K)
{
    GEMM_MAINLOOP(Ah, Bh, K)

    const int g  = lane >> 2;
    const int t4 = lane & 3;
#pragma unroll
    for (int mi = 0; mi < 4; mi++) {
#pragma unroll
        for (int ni = 0; ni < 4; ni++) {
            const int col = bn + wn * 32 + ni * 8 + t4 * 2;
            const long r0 = bm + wm * 64 + mi * 16 + g;
            float2 bb = *(const float2*)&bias[col];
            float2 o0 = { acc[mi][ni][0] + bb.x, acc[mi][ni][1] + bb.y };
            float2 o1 = { acc[mi][ni][2] + bb.x, acc[mi][ni][3] + bb.y };
            *(float2*)&C[r0 * N + col] = o0;
            *(float2*)&C[(r0 + 8) * N + col] = o1;
        }
    }
}

// ---------------------------------------------------------------------------
// QKV GEMM: epilogue writes Q(scaled)/K/V fp16 trunc directly to [b,h,s,d].
// ---------------------------------------------------------------------------
__global__ void __launch_bounds__(256, 2) gemm_qkv(
    const __half* __restrict__ Ah, const __half* __restrict__ Bh,
    const float* __restrict__ bias,
    __half* __restrict__ Qh, __half* __restrict__ Kh, __half* __restrict__ Vh,
    int K)
{
    GEMM_MAINLOOP(Ah, Bh, K)

    const int g  = lane >> 2;
    const int t4 = lane & 3;
    const int region = bn >> 10;            // 0=Q 1=K 2=V
    __half* Dh;
    float scale = 1.f;
    if (region == 0) { Dh = Qh; scale = 0.125f; }
    else if (region == 1) { Dh = Kh; }
    else { Dh = Vh; }

#pragma unroll
    for (int mi = 0; mi < 4; mi++) {
#pragma unroll
        for (int ni = 0; ni < 4; ni++) {
            const int colg = bn + wn * 32 + ni * 8 + t4 * 2;
            const int c    = colg & 1023;
            const int h    = c >> 6, d = c & 63;
            const long r0  = bm + wm * 64 + mi * 16 + g;       // = b*S + s
            const int b    = (int)(r0 >> 10);
            const int s    = (int)(r0 & 1023);
            float2 bb = *(const float2*)&bias[colg];
            long o = (((long)b * H_ + h) * S_ + s) * D_ + d;
            *(__half2*)&Dh[o] =
                __half2(__float2half((acc[mi][ni][0] + bb.x) * scale),
                        __float2half((acc[mi][ni][1] + bb.y) * scale));
            *(__half2*)&Dh[o + 8 * D_] =
                __half2(__float2half((acc[mi][ni][2] + bb.x) * scale),
                        __float2half((acc[mi][ni][3] + bb.y) * scale));
        }
    }
}

// ---------------------------------------------------------------------------
// Causal flash-attention: 128-row Q tiles, warp-private softmax, 128-wide K/V
// tiles (two 64-halves per load), double-buffered, ONE sync per 128 k.
// ---------------------------------------------------------------------------
#define ATS 72                                   // halfs per smem row (144 B)
#define Q_H 0                                    // 128 rows
#define KV0 (128 * ATS)                          // stage: K 128 rows + V 128 rows
#define KVS (256 * ATS)
#define ATTN2_SMEM ((128 + 2 * 256) * ATS * 2)   // 92160 B -> 2 CTAs/SM

__global__ void __launch_bounds__(256, 2) attn_mma(
    const __half* __restrict__ Qh, const __half* __restrict__ Kh,
    const __half* __restrict__ Vh, __half* __restrict__ Oh)
{
    extern __shared__ __align__(128) char asmem[];
    const uint32_t sb = smem_to_u32(asmem);

    const int tid  = threadIdx.x;
    const int lane = tid & 31;
    const int wid  = tid >> 5;               // 8 warps, 16 q-rows each
    const int qtile = 7 - (int)blockIdx.x;   // big work first (tail packing)
    const int h    = blockIdx.y;
    const int b    = blockIdx.z;
    const int q0   = qtile * 128;
    const long bh  = (long)b * H_ + h;

    const int g    = lane >> 2;
    const int t4   = lane & 3;
    const int row0 = q0 + wid * 16 + g;      // global q row
    const int row1 = row0 + 8;

    // ---- Q tile (128 rows x 64)
    {
        const __half* qs = Qh + (bh * S_ + q0) * D_;
#pragma unroll
        for (int j = 0; j < 4; j++) {
            int lin = tid + j * 256;
            int r = lin >> 3, c = lin & 7;
            cp_async16(sb + (Q_H + r * ATS) * 2 + c * 16, qs + (long)r * D_ + c * 8);
        }
    }
    // K/V tile: 128 rows each per stage
    auto load_kv = [&](int kt) {
        const uint32_t base = KV0 + (kt & 1) * KVS;
        const __half* ks = Kh + (bh * S_ + kt * 128) * D_;
        const __half* vs = Vh + (bh * S_ + kt * 128) * D_;
#pragma unroll
        for (int j = 0; j < 4; j++) {
            int lin = tid + j * 256;
            int r = lin >> 3, c = lin & 7;
            cp_async16(sb + (base + r * ATS) * 2 + c * 16, ks + (long)r * D_ + c * 8);
            cp_async16(sb + (base + (128 + r) * ATS) * 2 + c * 16, vs + (long)r * D_ + c * 8);
        }
    };
    load_kv(0);
    CP_COMMIT();

    float m2[2] = { -1e30f, -1e30f }, l2[2] = { 0.f, 0.f };
    float oacc[8][4];
#pragma unroll
    for (int nt = 0; nt < 8; nt++)
#pragma unroll
        for (int r = 0; r < 4; r++) oacc[nt][r] = 0.f;

    const int arow = wid * 16 + (lane & 15);
    const int asel = (lane >> 4) << 3;
    const int brow = (lane & 7) + ((lane >> 4) << 3);
    const int bsel = ((lane >> 3) & 1) << 3;
    const int vrow = ((lane >> 3) & 1) * 8 + (lane & 7);
    const int vcol = (lane >> 4) << 3;

    const int NT = qtile + 1;                // 128-wide k-tiles

    for (int kt = 0; kt < NT; kt++) {
        CP_WAIT(0);
        __syncthreads();
        if (kt + 1 < NT) {
            load_kv(kt + 1);
            CP_COMMIT();
        }
        const uint32_t kbase = KV0 + (kt & 1) * KVS;

#pragma unroll
        for (int hf = 0; hf < 2; hf++) {
            const uint32_t kbuf = kbase + hf * 64 * ATS;
            const uint32_t vbuf = kbase + (128 + hf * 64) * ATS;

            // ---- S = Q @ K^T : warp covers 16 q-rows x 64 k-cols
            float s[8][4];
#pragma unroll
            for (int ni = 0; ni < 8; ni++)
#pragma unroll
                for (int r = 0; r < 4; r++) s[ni][r] = 0.f;

#pragma unroll
            for (int ks = 0; ks < 4; ks++) {
                const int acol = ks * 16 + asel;
                const int bcol = ks * 16 + bsel;
                uint32_t a[4], bq[8][2];
                ldsm_x4(a[0], a[1], a[2], a[3], sb + (Q_H + arow * ATS + acol) * 2);
#pragma unroll
                for (int nj = 0; nj < 4; nj++)
                    ldsm_x4(bq[nj * 2][0], bq[nj * 2][1], bq[nj * 2 + 1][0], bq[nj * 2 + 1][1],
                            sb + (kbuf + (brow + nj * 16) * ATS + bcol) * 2);
#pragma unroll
                for (int ni = 0; ni < 8; ni++)
                    mma16816h(s[ni], a, bq[ni]);
            }

            // ---- causal mask (only final k-tile touches the diagonal)
            if (kt == qtile) {
                const int cb = kt * 128 + hf * 64;
#pragma unroll
                for (int ni = 0; ni < 8; ni++) {
                    const int col = cb + ni * 8 + t4 * 2;
                    if (col > row0)     s[ni][0] = -1e9f;
                    if (col + 1 > row0) s[ni][1] = -1e9f;
                    if (col > row1)     s[ni][2] = -1e9f;
                    if (col + 1 > row1) s[ni][3] = -1e9f;
                }
            }

            // ---- warp-private online softmax (quad shfl)
            float mx0 = -1e30f, mx1 = -1e30f;
#pragma unroll
            for (int ni = 0; ni < 8; ni++) {
                mx0 = fmaxf(mx0, fmaxf(s[ni][0], s[ni][1]));
                mx1 = fmaxf(mx1, fmaxf(s[ni][2], s[ni][3]));
            }
            mx0 = fmaxf(mx0, __shfl_xor_sync(0xffffffffu, mx0, 1));
            mx0 = fmaxf(mx0, __shfl_xor_sync(0xffffffffu, mx0, 2));
            mx1 = fmaxf(mx1, __shfl_xor_sync(0xffffffffu, mx1, 1));
            mx1 = fmaxf(mx1, __shfl_xor_sync(0xffffffffu, mx1, 2));
            const float mn0 = fmaxf(m2[0], mx0), mn1 = fmaxf(m2[1], mx1);
            const float alpha0 = __expf(m2[0] - mn0), alpha1 = __expf(m2[1] - mn1);
            m2[0] = mn0; m2[1] = mn1;

            float rs0 = 0.f, rs1 = 0.f;
#pragma unroll
            for (int ni = 0; ni < 8; ni++) {
                s[ni][0] = __expf(s[ni][0] - mn0);
                s[ni][1] = __expf(s[ni][1] - mn0);
                s[ni][2] = __expf(s[ni][2] - mn1);
                s[ni][3] = __expf(s[ni][3] - mn1);
                rs0 += s[ni][0] + s[ni][1];
                rs1 += s[ni][2] + s[ni][3];
            }
            rs0 += __shfl_xor_sync(0xffffffffu, rs0, 1);
            rs0 += __shfl_xor_sync(0xffffffffu, rs0, 2);
            rs1 += __shfl_xor_sync(0xffffffffu, rs1, 1);
            rs1 += __shfl_xor_sync(0xffffffffu, rs1, 2);
            l2[0] = l2[0] * alpha0 + rs0;
            l2[1] = l2[1] * alpha1 + rs1;

            // ---- O = O*alpha + P @ V
#pragma unroll
            for (int nt = 0; nt < 8; nt++) {
                oacc[nt][0] *= alpha0; oacc[nt][1] *= alpha0;
                oacc[nt][2] *= alpha1; oacc[nt][3] *= alpha1;
            }
#pragma unroll
            for (int j = 0; j < 4; j++) {
                uint32_t pa[4];
                pa[0] = packh2(s[2 * j][0],     s[2 * j][1]);
                pa[1] = packh2(s[2 * j][2],     s[2 * j][3]);
                pa[2] = packh2(s[2 * j + 1][0], s[2 * j + 1][1]);
                pa[3] = packh2(s[2 * j + 1][2], s[2 * j + 1][3]);
                const int kb = j * 16;
                uint32_t bv[8][2];
#pragma unroll
                for (int nj = 0; nj < 4; nj++)
                    ldsm_x4t(bv[nj * 2][0], bv[nj * 2][1], bv[nj * 2 + 1][0], bv[nj * 2 + 1][1],
                             sb + (vbuf + (kb + vrow) * ATS + vcol + nj * 16) * 2);
#pragma unroll
                for (int nt = 0; nt < 8; nt++)
                    mma16816h(oacc[nt], pa, bv[nt]);
            }
        }
    }

    // ---- epilogue: warp-private normalize + write
    const float inv0 = 1.f / l2[0], inv1 = 1.f / l2[1];
    const long r0 = (long)b * S_ + row0;
#pragma unroll
    for (int nt = 0; nt < 8; nt++) {
        const int col = h * D_ + nt * 8 + t4 * 2;
        *(__half2*)&Oh[r0 * NX_ + col] =
            __half2(__float2half(oacc[nt][0] * inv0), __float2half(oacc[nt][1] * inv0));
        *(__half2*)&Oh[(r0 + 8) * NX_ + col] =
            __half2(__float2half(oacc[nt][2] * inv1), __float2half(oacc[nt][3] * inv1));
    }
}

// ---------------------------------------------------------------------------
extern "C" void kernel_launch(void* const* d_in, const int* in_sizes, int n_in,
                              void* d_out, int out_size)
{
    const float* x      = (const float*)d_in[0];
    const float* w_attn = (const float*)d_in[1];
    const float* b_attn = (const float*)d_in[2];
    const float* w_proj = (const float*)d_in[3];
    const float* b_proj = (const float*)d_in[4];
    float* out = (float*)d_out;

    __half *xh, *ah, *wqh, *wph, *qh, *kh, *vh;
    cudaGetSymbolAddress((void**)&xh, g_xh);
    cudaGetSymbolAddress((void**)&ah, g_ah);
    cudaGetSymbolAddress((void**)&wqh, g_wqkv_h);
    cudaGetSymbolAddress((void**)&wph, g_wproj_h);
    cudaGetSymbolAddress((void**)&qh, g_qh);
    cudaGetSymbolAddress((void**)&kh, g_kh);
    cudaGetSymbolAddress((void**)&vh, g_vh);

    cudaFuncSetAttribute(attn_mma,
                         cudaFuncAttributeMaxDynamicSharedMemorySize, ATTN2_SMEM);
    cudaFuncSetAttribute(gemm_qkv,
                         cudaFuncAttributeMaxDynamicSharedMemorySize, GEMM_SMEM_DYN);
    cudaFuncSetAttribute(gemm_proj,
                         cudaFuncAttributeMaxDynamicSharedMemorySize, GEMM_SMEM_DYN);

    const int M = B_ * S_;  // 8192

    // truncate x to fp16
    {
        int n4 = M * NX_ / 4;
        trunc_kernel<<<(n4 + 255) / 256, 256>>>(x, xh, n4);
    }
    // transpose+truncate weights (fp16)
    tsplit_kernel<<<dim3(3 * NX_ / 32, NX_ / 32), dim3(32, 8)>>>(w_attn, wqh, NX_, 3 * NX_);
    tsplit_kernel<<<dim3(NX_ / 32, NX_ / 32), dim3(32, 8)>>>(w_proj, wph, NX_, NX_);

    // QKV GEMM (single-product fp16, 3-stage) with fused fp16 epilogue
    gemm_qkv<<<dim3(3 * NX_ / 128, M / 128), 256, GEMM_SMEM_DYN>>>(
        xh, wqh, b_attn, qh, kh, vh, NX_);

    // attention (128-row Q tiles, 128-wide K/V tiles) -> fp16 trunc
    attn_mma<<<dim3(S_ / 128, H_, B_), 256, ATTN2_SMEM>>>(qh, kh, vh, ah);

    // projection GEMM (single-product fp16, 3-stage) -> final fp32 output
    gemm_proj<<<dim3(NX_ / 128, M / 128), 256, GEMM_SMEM_DYN>>>(
        ah, wph, b_proj, out, NX_, NX_);
}

// round 17
// speedup vs baseline: 1.0128x; 1.0128x over previous
#include <cuda_runtime.h>
#include <cuda_bf16.h>
#include <cuda_fp16.h>
#include <cstdint>

#define B_  8
#define S_  1024
#define NX_ 1024
#define H_  16
#define D_  64

// ---------------- scratch (__device__ globals; no allocation) ----------------
__device__ __half g_xh[B_ * S_ * NX_];               // x, fp16 trunc
__device__ __half g_ah[B_ * S_ * NX_];               // attention out, fp16 trunc
__device__ __half g_wqkv_h[3 * NX_ * NX_];           // [N=3072, K=1024] fp16 trunc
__device__ __half g_wproj_h[NX_ * NX_];              // [N=1024, K=1024]
__device__ __half g_qh[B_ * H_ * S_ * D_];           // [b,h,s,d], pre-scaled 0.125
__device__ __half g_kh[B_ * H_ * S_ * D_];
__device__ __half g_vh[B_ * H_ * S_ * D_];

// ---------------- PTX helpers ----------------
__device__ __forceinline__ uint32_t smem_to_u32(const void* p) {
    uint32_t a;
    asm("{ .reg .u64 t; cvta.to.shared.u64 t, %1; cvt.u32.u64 %0, t; }"
        : "=r"(a) : "l"(p));
    return a;
}
__device__ __forceinline__ void cp_async16(uint32_t dst, const void* src) {
    asm volatile("cp.async.cg.shared.global [%0], [%1], 16;"
                 :: "r"(dst), "l"(src) : "memory");
}
#define CP_COMMIT() asm volatile("cp.async.commit_group;" ::: "memory")
#define CP_WAIT(n)  asm volatile("cp.async.wait_group %0;" :: "n"(n) : "memory")

__device__ __forceinline__ void ldsm_x4(uint32_t& r0, uint32_t& r1,
                                        uint32_t& r2, uint32_t& r3, uint32_t addr) {
    asm volatile("ldmatrix.sync.aligned.m8n8.x4.shared.b16 {%0,%1,%2,%3}, [%4];"
                 : "=r"(r0), "=r"(r1), "=r"(r2), "=r"(r3) : "r"(addr));
}
__device__ __forceinline__ void ldsm_x4t(uint32_t& r0, uint32_t& r1,
                                         uint32_t& r2, uint32_t& r3, uint32_t addr) {
    asm volatile("ldmatrix.sync.aligned.m8n8.x4.trans.shared.b16 {%0,%1,%2,%3}, [%4];"
                 : "=r"(r0), "=r"(r1), "=r"(r2), "=r"(r3) : "r"(addr));
}
__device__ __forceinline__ void mma16816h(float* c, const uint32_t* a, const uint32_t* b) {
    asm volatile("mma.sync.aligned.m16n8k16.row.col.f32.f16.f16.f32 "
                 "{%0,%1,%2,%3}, {%4,%5,%6,%7}, {%8,%9}, {%0,%1,%2,%3};"
                 : "+f"(c[0]), "+f"(c[1]), "+f"(c[2]), "+f"(c[3])
                 : "r"(a[0]), "r"(a[1]), "r"(a[2]), "r"(a[3]),
                   "r"(b[0]), "r"(b[1]));
}
__device__ __forceinline__ uint32_t packh2(float x, float y) {
    __half2 h = __halves2half2(__float2half(x), __float2half(y));
    return *(uint32_t*)&h;
}

// ---------------------------------------------------------------------------
// truncate: fp32 -> fp16, same layout.
// ---------------------------------------------------------------------------
__global__ void trunc_kernel(const float* __restrict__ in,
                             __half* __restrict__ h, int n4)
{
    int i = blockIdx.x * blockDim.x + threadIdx.x;
    if (i >= n4) return;
    float4 v = ((const float4*)in)[i];
    ((__half2*)h)[2 * i]     = __half2(__float2half(v.x), __float2half(v.y));
    ((__half2*)h)[2 * i + 1] = __half2(__float2half(v.z), __float2half(v.w));
}

// ---------------------------------------------------------------------------
// transpose + truncate: W[K,N] fp32 -> T_h [N,K] fp16
// ---------------------------------------------------------------------------
__global__ void tsplit_kernel(const float* __restrict__ W,
                              __half* __restrict__ Th, int K, int N)
{
    __shared__ float t[32][33];
    int n0 = blockIdx.x * 32, k0 = blockIdx.y * 32;
    int tx = threadIdx.x, ty = threadIdx.y;  // 32 x 8
#pragma unroll
    for (int i = 0; i < 4; i++)
        t[ty + i * 8][tx] = W[(long)(k0 + ty + i * 8) * N + n0 + tx];
    __syncthreads();
#pragma unroll
    for (int i = 0; i < 4; i++) {
        float v = t[tx][ty + i * 8];
        Th[(long)(n0 + ty + i * 8) * K + k0 + tx] = __float2half(v);
    }
}

// ---------------------------------------------------------------------------
// GEMM mainloop: single-product fp16, 128x128x64 CTA tile, 256 threads,
// 8 warps (2Mx4N), 2-stage cp.async, ONE sync per stage. (R15 shape, best.)
// ---------------------------------------------------------------------------
#define ROWB    144
#define TILE_B  (128 * ROWB)
#define STAGE_B (2 * TILE_B)
#define GEMM_SMEM_DYN (2 * STAGE_B)

#define GEMM_MAINLOOP(Ah, Bh, K)                                                \
    extern __shared__ __align__(128) char smem[];                               \
    const uint32_t sbase = smem_to_u32(smem);                                   \
    const int tid  = threadIdx.x;                                               \
    const int lane = tid & 31;                                                  \
    const int wid  = tid >> 5;                                                  \
    const int wm   = wid & 1;                                                   \
    const int wn   = wid >> 1;                                                  \
    const int bm   = blockIdx.y * 128;                                          \
    const int bn   = blockIdx.x * 128;                                          \
    float acc[4][4][4];                                                         \
    _Pragma("unroll")                                                           \
    for (int mi = 0; mi < 4; mi++)                                              \
        _Pragma("unroll")                                                       \
        for (int ni = 0; ni < 4; ni++)                                          \
            _Pragma("unroll")                                                   \
            for (int r = 0; r < 4; r++) acc[mi][ni][r] = 0.f;                   \
    const __half* gA = Ah + (long)bm * (K);                                     \
    const __half* gB = Bh + (long)bn * (K);                                     \
    const int NS = (K) / 64;                                                    \
    auto load_stage = [&](int s) {                                              \
        const int k0 = s * 64;                                                  \
        const uint32_t buf = sbase + (s & 1) * STAGE_B;                         \
        _Pragma("unroll")                                                       \
        for (int p = 0; p < 4; p++) {                                           \
            int lin = tid + p * 256;                                            \
            int r = lin >> 3, c = lin & 7;                                      \
            cp_async16(buf + r * ROWB + c * 16,                                 \
                       gA + (long)r * (K) + k0 + c * 8);                        \
            cp_async16(buf + TILE_B + r * ROWB + c * 16,                        \
                       gB + (long)r * (K) + k0 + c * 8);                        \
        }                                                                       \
    };                                                                          \
    load_stage(0);                                                              \
    CP_COMMIT();                                                                \
    const int arow  = wm * 64 + (lane & 15);                                    \
    const int asel  = (lane >> 4) << 3;                                         \
    const int brow  = wn * 32 + (lane & 7) + ((lane >> 4) << 3);                \
    const int bsel  = ((lane >> 3) & 1) << 3;                                   \
    for (int s = 0; s < NS; s++) {                                              \
        CP_WAIT(0);                                                             \
        __syncthreads();                                                        \
        if (s + 1 < NS) {                                                       \
            load_stage(s + 1);                                                  \
            CP_COMMIT();                                                        \
        }                                                                       \
        const uint32_t buf = sbase + (s & 1) * STAGE_B;                         \
        _Pragma("unroll")                                                       \
        for (int ks = 0; ks < 4; ks++) {                                        \
            uint32_t a[4][4];                                                   \
            uint32_t b[4][2];                                                   \
            const int acol = ks * 16 + asel;                                    \
            const int bcol = ks * 16 + bsel;                                    \
            _Pragma("unroll")                                                   \
            for (int nj = 0; nj < 2; nj++)                                      \
                ldsm_x4(b[nj * 2][0], b[nj * 2][1],                             \
                        b[nj * 2 + 1][0], b[nj * 2 + 1][1],                     \
                        buf + TILE_B + (brow + nj * 16) * ROWB + bcol * 2);     \
            _Pragma("unroll")                                                   \
            for (int mi = 0; mi < 4; mi++)                                      \
                ldsm_x4(a[mi][0], a[mi][1], a[mi][2], a[mi][3],                 \
                        buf + (arow + mi * 16) * ROWB + acol * 2);              \
            _Pragma("unroll")                                                   \
            for (int mi = 0; mi < 4; mi++)                                      \
                _Pragma("unroll")                                               \
                for (int ni = 0; ni < 4; ni++)                                  \
                    mma16816h(acc[mi][ni], a[mi], b[ni]);                       \
        }                                                                       \
    }

// ---------------------------------------------------------------------------
// Projection GEMM: fp32 out + bias (final output)
// ---------------------------------------------------------------------------
__global__ void __launch_bounds__(256, 2) gemm_proj(
    const __half* __restrict__ Ah, const __half* __restrict__ Bh,
    const float* __restrict__ bias, float* __restrict__ C, int N, int K)
{
    GEMM_MAINLOOP(Ah, Bh, K)

    const int g  = lane >> 2;
    const int t4 = lane & 3;
#pragma unroll
    for (int mi = 0; mi < 4; mi++) {
#pragma unroll
        for (int ni = 0; ni < 4; ni++) {
            const int col = bn + wn * 32 + ni * 8 + t4 * 2;
            const long r0 = bm + wm * 64 + mi * 16 + g;
            float2 bb = *(const float2*)&bias[col];
            float2 o0 = { acc[mi][ni][0] + bb.x, acc[mi][ni][1] + bb.y };
            float2 o1 = { acc[mi][ni][2] + bb.x, acc[mi][ni][3] + bb.y };
            *(float2*)&C[r0 * N + col] = o0;
            *(float2*)&C[(r0 + 8) * N + col] = o1;
        }
    }
}

// ---------------------------------------------------------------------------
// QKV GEMM: epilogue writes Q(scaled)/K/V fp16 trunc directly to [b,h,s,d].
// ---------------------------------------------------------------------------
__global__ void __launch_bounds__(256, 2) gemm_qkv(
    const __half* __restrict__ Ah, const __half* __restrict__ Bh,
    const float* __restrict__ bias,
    __half* __restrict__ Qh, __half* __restrict__ Kh, __half* __restrict__ Vh,
    int K)
{
    GEMM_MAINLOOP(Ah, Bh, K)

    const int g  = lane >> 2;
    const int t4 = lane & 3;
    const int region = bn >> 10;            // 0=Q 1=K 2=V
    __half* Dh;
    float scale = 1.f;
    if (region == 0) { Dh = Qh; scale = 0.125f; }
    else if (region == 1) { Dh = Kh; }
    else { Dh = Vh; }

#pragma unroll
    for (int mi = 0; mi < 4; mi++) {
#pragma unroll
        for (int ni = 0; ni < 4; ni++) {
            const int colg = bn + wn * 32 + ni * 8 + t4 * 2;
            const int c    = colg & 1023;
            const int h    = c >> 6, d = c & 63;
            const long r0  = bm + wm * 64 + mi * 16 + g;       // = b*S + s
            const int b    = (int)(r0 >> 10);
            const int s    = (int)(r0 & 1023);
            float2 bb = *(const float2*)&bias[colg];
            long o = (((long)b * H_ + h) * S_ + s) * D_ + d;
            *(__half2*)&Dh[o] =
                __half2(__float2half((acc[mi][ni][0] + bb.x) * scale),
                        __float2half((acc[mi][ni][1] + bb.y) * scale));
            *(__half2*)&Dh[o + 8 * D_] =
                __half2(__float2half((acc[mi][ni][2] + bb.x) * scale),
                        __float2half((acc[mi][ni][3] + bb.y) * scale));
        }
    }
}

// ---------------------------------------------------------------------------
// Causal flash-attention: 128-row Q tiles, warp-private softmax, 64-wide K/V
// tiles with a 3-buffer cp.async pipeline (wait_group 1) — two tiles of cover.
// ---------------------------------------------------------------------------
#define ATS 72                                   // halfs per smem row (144 B)
#define Q_H 0                                    // 128 rows
#define KV0 (128 * ATS)                          // stage s: K 64 rows + V 64 rows
#define KVS (128 * ATS)
#define ATTN2_SMEM ((128 + 3 * 128) * ATS * 2)   // 73728 B -> 2 CTAs/SM

__global__ void __launch_bounds__(256, 2) attn_mma(
    const __half* __restrict__ Qh, const __half* __restrict__ Kh,
    const __half* __restrict__ Vh, __half* __restrict__ Oh)
{
    extern __shared__ __align__(128) char asmem[];
    const uint32_t sb = smem_to_u32(asmem);

    const int tid  = threadIdx.x;
    const int lane = tid & 31;
    const int wid  = tid >> 5;               // 8 warps, 16 q-rows each
    const int qtile = 7 - (int)blockIdx.x;   // big work first (tail packing)
    const int h    = blockIdx.y;
    const int b    = blockIdx.z;
    const int q0   = qtile * 128;
    const long bh  = (long)b * H_ + h;

    const int g    = lane >> 2;
    const int t4   = lane & 3;
    const int row0 = q0 + wid * 16 + g;      // global q row
    const int row1 = row0 + 8;

    const int NT = 2 * qtile + 2;            // 64-wide k-tiles

    // ---- Q tile (128 rows x 64), grouped with KV stage 0
    {
        const __half* qs = Qh + (bh * S_ + q0) * D_;
#pragma unroll
        for (int j = 0; j < 4; j++) {
            int lin = tid + j * 256;
            int r = lin >> 3, c = lin & 7;
            cp_async16(sb + (Q_H + r * ATS) * 2 + c * 16, qs + (long)r * D_ + c * 8);
        }
    }
    auto load_kv = [&](int kt) {
        const uint32_t base = KV0 + (kt % 3) * KVS;
        const __half* ks = Kh + (bh * S_ + kt * 64) * D_;
        const __half* vs = Vh + (bh * S_ + kt * 64) * D_;
#pragma unroll
        for (int j = 0; j < 2; j++) {
            int lin = tid + j * 256;
            int r = lin >> 3, c = lin & 7;
            cp_async16(sb + (base + r * ATS) * 2 + c * 16, ks + (long)r * D_ + c * 8);
            cp_async16(sb + (base + (64 + r) * ATS) * 2 + c * 16, vs + (long)r * D_ + c * 8);
        }
    };
    load_kv(0);
    CP_COMMIT();
    if (1 < NT) {
        load_kv(1);
        CP_COMMIT();
    }

    float m2[2] = { -1e30f, -1e30f }, l2[2] = { 0.f, 0.f };
    float oacc[8][4];
#pragma unroll
    for (int nt = 0; nt < 8; nt++)
#pragma unroll
        for (int r = 0; r < 4; r++) oacc[nt][r] = 0.f;

    const int arow = wid * 16 + (lane & 15);
    const int asel = (lane >> 4) << 3;
    const int brow = (lane & 7) + ((lane >> 4) << 3);
    const int bsel = ((lane >> 3) & 1) << 3;
    const int vrow = ((lane >> 3) & 1) * 8 + (lane & 7);
    const int vcol = (lane >> 4) << 3;

    for (int kt = 0; kt < NT; kt++) {
        if (kt + 1 < NT) { CP_WAIT(1); } else { CP_WAIT(0); }
        __syncthreads();
        if (kt + 2 < NT) {
            load_kv(kt + 2);
            CP_COMMIT();
        }
        const uint32_t kbuf = KV0 + (kt % 3) * KVS;
        const uint32_t vbuf = kbuf + 64 * ATS;

        // ---- S = Q @ K^T : warp covers 16 q-rows x 64 k-cols
        float s[8][4];
#pragma unroll
        for (int ni = 0; ni < 8; ni++)
#pragma unroll
            for (int r = 0; r < 4; r++) s[ni][r] = 0.f;

#pragma unroll
        for (int ks = 0; ks < 4; ks++) {
            const int acol = ks * 16 + asel;
            const int bcol = ks * 16 + bsel;
            uint32_t a[4], bq[8][2];
            ldsm_x4(a[0], a[1], a[2], a[3], sb + (Q_H + arow * ATS + acol) * 2);
#pragma unroll
            for (int nj = 0; nj < 4; nj++)
                ldsm_x4(bq[nj * 2][0], bq[nj * 2][1], bq[nj * 2 + 1][0], bq[nj * 2 + 1][1],
                        sb + (kbuf + (brow + nj * 16) * ATS + bcol) * 2);
#pragma unroll
            for (int ni = 0; ni < 8; ni++)
                mma16816h(s[ni], a, bq[ni]);
        }

        // ---- causal mask (only the last two k-tiles can touch the diagonal)
        if (kt >= 2 * qtile) {
            const int cb = kt * 64;
#pragma unroll
            for (int ni = 0; ni < 8; ni++) {
                const int col = cb + ni * 8 + t4 * 2;
                if (col > row0)     s[ni][0] = -1e9f;
                if (col + 1 > row0) s[ni][1] = -1e9f;
                if (col > row1)     s[ni][2] = -1e9f;
                if (col + 1 > row1) s[ni][3] = -1e9f;
            }
        }

        // ---- warp-private online softmax (quad shfl)
        float mx0 = -1e30f, mx1 = -1e30f;
#pragma unroll
        for (int ni = 0; ni < 8; ni++) {
            mx0 = fmaxf(mx0, fmaxf(s[ni][0], s[ni][1]));
            mx1 = fmaxf(mx1, fmaxf(s[ni][2], s[ni][3]));
        }
        mx0 = fmaxf(mx0, __shfl_xor_sync(0xffffffffu, mx0, 1));
        mx0 = fmaxf(mx0, __shfl_xor_sync(0xffffffffu, mx0, 2));
        mx1 = fmaxf(mx1, __shfl_xor_sync(0xffffffffu, mx1, 1));
        mx1 = fmaxf(mx1, __shfl_xor_sync(0xffffffffu, mx1, 2));
        const float mn0 = fmaxf(m2[0], mx0), mn1 = fmaxf(m2[1], mx1);
        const float alpha0 = __expf(m2[0] - mn0), alpha1 = __expf(m2[1] - mn1);
        m2[0] = mn0; m2[1] = mn1;

        float rs0 = 0.f, rs1 = 0.f;
#pragma unroll
        for (int ni = 0; ni < 8; ni++) {
            s[ni][0] = __expf(s[ni][0] - mn0);
            s[ni][1] = __expf(s[ni][1] - mn0);
            s[ni][2] = __expf(s[ni][2] - mn1);
            s[ni][3] = __expf(s[ni][3] - mn1);
            rs0 += s[ni][0] + s[ni][1];
            rs1 += s[ni][2] + s[ni][3];
        }
        rs0 += __shfl_xor_sync(0xffffffffu, rs0, 1);
        rs0 += __shfl_xor_sync(0xffffffffu, rs0, 2);
        rs1 += __shfl_xor_sync(0xffffffffu, rs1, 1);
        rs1 += __shfl_xor_sync(0xffffffffu, rs1, 2);
        l2[0] = l2[0] * alpha0 + rs0;
        l2[1] = l2[1] * alpha1 + rs1;

        // ---- O = O*alpha + P @ V (all 64 k, all 64 d)
#pragma unroll
        for (int nt = 0; nt < 8; nt++) {
            oacc[nt][0] *= alpha0; oacc[nt][1] *= alpha0;
            oacc[nt][2] *= alpha1; oacc[nt][3] *= alpha1;
        }
#pragma unroll
        for (int j = 0; j < 4; j++) {
            uint32_t pa[4];
            pa[0] = packh2(s[2 * j][0],     s[2 * j][1]);
            pa[1] = packh2(s[2 * j][2],     s[2 * j][3]);
            pa[2] = packh2(s[2 * j + 1][0], s[2 * j + 1][1]);
            pa[3] = packh2(s[2 * j + 1][2], s[2 * j + 1][3]);
            const int kb = j * 16;
            uint32_t bv[8][2];
#pragma unroll
            for (int nj = 0; nj < 4; nj++)
                ldsm_x4t(bv[nj * 2][0], bv[nj * 2][1], bv[nj * 2 + 1][0], bv[nj * 2 + 1][1],
                         sb + (vbuf + (kb + vrow) * ATS + vcol + nj * 16) * 2);
#pragma unroll
            for (int nt = 0; nt < 8; nt++)
                mma16816h(oacc[nt], pa, bv[nt]);
        }
    }

    // ---- epilogue: warp-private normalize + write
    const float inv0 = 1.f / l2[0], inv1 = 1.f / l2[1];
    const long r0 = (long)b * S_ + row0;
#pragma unroll
    for (int nt = 0; nt < 8; nt++) {
        const int col = h * D_ + nt * 8 + t4 * 2;
        *(__half2*)&Oh[r0 * NX_ + col] =
            __half2(__float2half(oacc[nt][0] * inv0), __float2half(oacc[nt][1] * inv0));
        *(__half2*)&Oh[(r0 + 8) * NX_ + col] =
            __half2(__float2half(oacc[nt][2] * inv1), __float2half(oacc[nt][3] * inv1));
    }
}

// ---------------------------------------------------------------------------
extern "C" void kernel_launch(void* const* d_in, const int* in_sizes, int n_in,
                              void* d_out, int out_size)
{
    const float* x      = (const float*)d_in[0];
    const float* w_attn = (const float*)d_in[1];
    const float* b_attn = (const float*)d_in[2];
    const float* w_proj = (const float*)d_in[3];
    const float* b_proj = (const float*)d_in[4];
    float* out = (float*)d_out;

    __half *xh, *ah, *wqh, *wph, *qh, *kh, *vh;
    cudaGetSymbolAddress((void**)&xh, g_xh);
    cudaGetSymbolAddress((void**)&ah, g_ah);
    cudaGetSymbolAddress((void**)&wqh, g_wqkv_h);
    cudaGetSymbolAddress((void**)&wph, g_wproj_h);
    cudaGetSymbolAddress((void**)&qh, g_qh);
    cudaGetSymbolAddress((void**)&kh, g_kh);
    cudaGetSymbolAddress((void**)&vh, g_vh);

    cudaFuncSetAttribute(attn_mma,
                         cudaFuncAttributeMaxDynamicSharedMemorySize, ATTN2_SMEM);
    cudaFuncSetAttribute(gemm_qkv,
                         cudaFuncAttributeMaxDynamicSharedMemorySize, GEMM_SMEM_DYN);
    cudaFuncSetAttribute(gemm_proj,
                         cudaFuncAttributeMaxDynamicSharedMemorySize, GEMM_SMEM_DYN);

    const int M = B_ * S_;  // 8192

    // truncate x to fp16
    {
        int n4 = M * NX_ / 4;
        trunc_kernel<<<(n4 + 255) / 256, 256>>>(x, xh, n4);
    }
    // transpose+truncate weights (fp16)
    tsplit_kernel<<<dim3(3 * NX_ / 32, NX_ / 32), dim3(32, 8)>>>(w_attn, wqh, NX_, 3 * NX_);
    tsplit_kernel<<<dim3(NX_ / 32, NX_ / 32), dim3(32, 8)>>>(w_proj, wph, NX_, NX_);

    // QKV GEMM (single-product fp16, 2-stage) with fused fp16 epilogue
    gemm_qkv<<<dim3(3 * NX_ / 128, M / 128), 256, GEMM_SMEM_DYN>>>(
        xh, wqh, b_attn, qh, kh, vh, NX_);

    // attention (128-row Q tiles, 3-buffer K/V pipeline) -> fp16 trunc
    attn_mma<<<dim3(S_ / 128, H_, B_), 256, ATTN2_SMEM>>>(qh, kh, vh, ah);

    // projection GEMM (single-product fp16, 2-stage) -> final fp32 output
    gemm_proj<<<dim3(NX_ / 128, M / 128), 256, GEMM_SMEM_DYN>>>(
        ah, wph, b_proj, out, NX_, NX_);
}